// round 6
// baseline (speedup 1.0000x reference)
#include <cuda_runtime.h>

// CTC loss forward, two-phase with producer/consumer scan.
//  Phase 1 (full chip): gather + exp emissions into g_em[b][t][0..31]=exp(lp[t,b,c1(l)]),
//    [32]=exp(lp[t,b,blank]). Spreads the scattered-load wavefronts over all SMs.
//  Phase 2 (64 blocks x 2 warps): producer warp streams g_em[b] (L2-resident, 33KB)
//    into SMEM with float4 LDGs, bar.arrive per 32-step chunk; consumer warp runs the
//    linear-domain fused-pair recursion off LDS (no LDG scoreboard stalls, no expf).
//    Exact pow2 rescale every 4 steps (redux.sync.max.s32 on float bits), lag-applied.

constexpr int T_SZ  = 256;
constexpr int B_SZ  = 64;
constexpr int C_SZ  = 8000;
constexpr int L_MAX = 32;
constexpr int ROW   = 33;                  // floats per timestep row in g_em/smem

__device__ float g_em[B_SZ][T_SZ][ROW];    // ~2.2MB, L2-resident
__device__ float g_loss[B_SZ];
__device__ int   g_count;

__device__ __forceinline__ int warp_max_s32(int v) {
    int r;
    asm volatile("redux.sync.max.s32 %0, %1, 0xffffffff;" : "=r"(r) : "r"(v));
    return r;
}
__device__ __forceinline__ float shup(float v, int d) {
    return __shfl_up_sync(0xffffffffu, v, d);
}

// ---------------- Phase 1: gather + exp ----------------
__global__ void __launch_bounds__(256)
ctc_gather(const float* __restrict__ lp,
           const int*   __restrict__ targets,
           const int*   __restrict__ tgt_len) {
    const int w = (blockIdx.x * 256 + threadIdx.x) >> 5;   // 0..B*T-1
    const int l = threadIdx.x & 31;
    const int b = w >> 8;
    const int t = w & 255;

    const int tl = tgt_len[b];
    const int c1 = (l < tl) ? targets[b * L_MAX + l] : 0;

    const float* base = lp + ((size_t)t * B_SZ + b) * C_SZ;
    g_em[b][t][l] = __expf(__ldg(base + c1));
    if (l == 0) g_em[b][t][32] = __expf(__ldg(base));
}

// ---------------- Phase 2: producer/consumer scan ----------------
__global__ void __launch_bounds__(64, 1)
ctc_scan(const int* __restrict__ targets,
         const int* __restrict__ in_len,
         const int* __restrict__ tgt_len,
         float*     __restrict__ out) {
    __shared__ float sm[T_SZ * ROW];       // 33792 B
    const int b = blockIdx.x;
    const int l = threadIdx.x & 31;
    const int w = threadIdx.x >> 5;

    // ---- producer warp: stream g_em[b] into smem, 8 chunks of 32 rows ----
    if (w == 1) {
        const float4* src = (const float4*)&g_em[b][0][0];
        float4*       dst = (float4*)sm;
        constexpr int PER = (T_SZ * ROW / 4) / 8;           // 264 float4 per chunk
        for (int c = 0; c < 8; c++) {
#pragma unroll 3
            for (int i = c * PER + l; i < (c + 1) * PER; i += 32)
                dst[i] = __ldg(src + i);
            __threadfence_block();
            asm volatile("bar.arrive %0, 64;" :: "r"(c + 1));
        }
        return;
    }

    // ---- consumer warp ----
    const int tl   = tgt_len[b];
    const int last = in_len[b] - 1;                         // in [128, 255]

    const int  c1   = (l < tl) ? targets[b * L_MAX + l] : 0;
    const int  c1p  = __shfl_up_sync(0xffffffffu, c1, 1);
    const bool skip = (c1 != 0) && ((l == 0) || (c1 != c1p));
    const float skf  = skip ? 1.f : 0.f;
    const float skfm = shup(skf, 1);
    const float m0   = (l == 0) ? 0.f : 1.f;
    const float m1   = (l <= 1) ? 0.f : 1.f;

    int sync_c = 0;
    asm volatile("bar.sync 1, 64;" ::: "memory");           // chunk 0 (rows 0..31)
    sync_c = 1;

    // t=0 init (prob domain, pre-scaled 2^80 for lagged-rescale headroom)
    float e = 0.f, o = 0.f, a2 = 0.f;
    if (l == 0) {
        e = sm[32] * 0x1p80f;                               // blank emission, row 0
        o = (tl > 0) ? sm[0] * 0x1p80f : 0.f;               // lane0 class emission
    }
    int g = 80;

    struct Q { float p1[4], pb[4], pmA, pmB; };
    auto loadq = [&](int q, Q& d) {
        const int r0 = 4 * q + 1;
#pragma unroll
        for (int j = 0; j < 4; j++) {
            int r = r0 + j; r = (r > 255) ? 255 : r;        // clamp: dup reads unused
            d.p1[j] = sm[r * ROW + l];
            d.pb[j] = sm[r * ROW + 32];
        }
        int rA = (r0     > 255) ? 255 : r0;
        int rB = (r0 + 2 > 255) ? 255 : (r0 + 2);
        // l==0 reads index -1 of the row (= previous row's blank slot): masked by m0
        d.pmA = sm[rA * ROW + l - 1] * m0;
        d.pmB = sm[rB * ROW + l - 1] * m0;
    };

    const int nq  = last >> 2;
    const int rem = last & 3;

    Q cur, nxt;
    loadq(0, cur);

    float fpend = 1.f;
    int   fexp  = 0;

    #pragma unroll 2
    for (int q = 0; q < nq; ++q) {
        // sync chunks covering prefetch rows <= 4q+8
        {
            int ch = 4 * q + 8; ch = (ch > 255) ? 255 : ch; ch >>= 5;
            while (sync_c <= ch) {
                asm volatile("bar.sync %0, 64;" :: "r"(sync_c + 1) : "memory");
                sync_c++;
            }
        }
        loadq(q + 1, nxt);                                  // LDS overlaps compute

        // lagged rescale: apply previous factor, measure next (redux off-chain)
        e *= fpend; o *= fpend; a2 *= fpend; g += fexp;
        {
            const int mi = warp_max_s32(__float_as_int(fmaxf(e, fmaxf(o, a2))));
            int fx = 207 - ((mi >> 23) & 0xff);             // 80 - E, exact pow2
            fx = fx > 127 ? 127 : (fx < -126 ? -126 : fx);
            fpend = __int_as_float((fx + 127) << 23);
            fexp  = fx;
        }

        // fused pair A: steps 4q+1, 4q+2
        {
            const float x1  = shup(o, 1) * m0;
            const float x2  = shup(o, 2) * m1;
            const float y1  = shup(e, 1);
            const float otm = ((x1 + y1) + skfm * x2) * cur.pmA;
            const float et  = (e + x1) * cur.pb[0];
            const float ot  = ((o + e) + skf * x1) * cur.p1[0];
            const float at  = (a2 + o) * cur.pb[0];
            e  = (et + otm) * cur.pb[1];
            o  = ((ot + et) + skf * otm) * cur.p1[1];
            a2 = (at + ot) * cur.pb[1];
        }
        // fused pair B: steps 4q+3, 4q+4
        {
            const float x1  = shup(o, 1) * m0;
            const float x2  = shup(o, 2) * m1;
            const float y1  = shup(e, 1);
            const float otm = ((x1 + y1) + skfm * x2) * cur.pmB;
            const float et  = (e + x1) * cur.pb[2];
            const float ot  = ((o + e) + skf * x1) * cur.p1[2];
            const float at  = (a2 + o) * cur.pb[2];
            e  = (et + otm) * cur.pb[3];
            o  = ((ot + et) + skf * otm) * cur.p1[3];
            a2 = (at + ot) * cur.pb[3];
        }
        cur = nxt;
    }

    // epilogue: up to 3 single steps (rows 4nq+1..last, already in cur + synced)
#pragma unroll
    for (int j = 0; j < 3; j++) {
        if (j < rem) {
            const float pa = shup(o, 1) * m0;
            const float en = (e + pa) * cur.pb[j];
            const float on = ((o + e) + skf * pa) * cur.p1[j];
            const float an = (a2 + o) * cur.pb[j];
            e = en; o = on; a2 = an;
        }
    }

    // final states: i_blank = 2*tl (e @ lane tl, or a2 @ lane31 if tl==32),
    //               i_char  = 2*tl-1 (o @ lane tl-1)
    const float vbl = __shfl_sync(0xffffffffu, e, tl & 31);
    const float vbh = __shfl_sync(0xffffffffu, a2, 31);
    const float vb  = (tl >= 32) ? vbh : vbl;
    const int   icl = (tl > 0) ? (tl - 1) : 0;
    const float vc  = __shfl_sync(0xffffffffu, o, icl);
    const float tot = (tl > 0) ? (vb + vc) : vb;

    if (l == 0) {
        const float total_log = logf(tot) - (float)g * 0.69314718055994531f;
        const int   denom     = (tl > 0) ? tl : 1;
        g_loss[b] = -total_log / (float)denom;
        __threadfence();
        const int old = atomicAdd(&g_count, 1);
        if (old == B_SZ - 1) {
            g_count = 0;                       // reset for next graph replay
            __threadfence();
            float s = 0.f;
            for (int i = 0; i < B_SZ; i++) s += __ldcg((const float*)&g_loss[i]);
            out[0] = s / (float)B_SZ;
        }
    }
}

extern "C" void kernel_launch(void* const* d_in, const int* in_sizes, int n_in,
                              void* d_out, int out_size) {
    const float* log_probs  = (const float*)d_in[0];
    const int*   targets    = (const int*)d_in[1];
    const int*   input_len  = (const int*)d_in[2];
    const int*   target_len = (const int*)d_in[3];
    float* out = (float*)d_out;
    (void)in_sizes; (void)n_in; (void)out_size;

    ctc_gather<<<(B_SZ * T_SZ) / 8, 256>>>(log_probs, targets, target_len);
    ctc_scan<<<B_SZ, 64>>>(targets, input_len, target_len, out);
}

// round 9
// speedup vs baseline: 1.0986x; 1.0986x over previous
#include <cuda_runtime.h>

// CTC loss forward, single fused kernel, producer/consumer within each block.
// 64 blocks (one per batch), 5 warps: warps 1-4 gather+exp emissions into a
// smem table sm[t][0..31]=exp(lp[t,b,c1(l)]), sm[t][32]=exp(lp[t,b,blank]),
// striped t%4, signalling named bars 1..4 after rows <72 / <136 / <200 / all
// (consumer segment s prefetches rows up to 68/132/196 — strictly covered).
// Warp 0 runs the linear-domain fused-pair recursion off LDS: lane l owns
// states 2l ("e") and 2l+1 ("o"); lane 31 also state 64 ("a2"). Exact pow2
// rescale EVERY 4 steps (redux.sync.max.s32 on float bits), lag-applied —
// the 4-step window bounds uncorrected drift so sub-max states never flush.

constexpr int B_SZ  = 64;
constexpr int C_SZ  = 8000;
constexpr int L_MAX = 32;
constexpr int ROW   = 33;

__device__ float g_loss[B_SZ];
__device__ int   g_count;

__device__ __forceinline__ int warp_max_s32(int v) {
    int r;
    asm volatile("redux.sync.max.s32 %0, %1, 0xffffffff;" : "=r"(r) : "r"(v));
    return r;
}
__device__ __forceinline__ float shup(float v, int d) {
    return __shfl_up_sync(0xffffffffu, v, d);
}

struct QB { float p1[4], pb[4], pmA, pmB; };

__device__ __forceinline__ void loadq(const float* __restrict__ sm, int q,
                                      int last, int l, float m0, QB& d) {
    const int r0 = 4 * q + 1;
#pragma unroll
    for (int j = 0; j < 4; j++) {
        const int r = min(r0 + j, last);
        d.p1[j] = sm[r * ROW + l];
        d.pb[j] = sm[r * ROW + 32];
    }
    const int rA = min(r0, last);
    const int rB = min(r0 + 2, last);
    // l==0 reads [r*ROW-1] = previous row's blank slot; masked by m0
    d.pmA = sm[rA * ROW + l - 1] * m0;
    d.pmB = sm[rB * ROW + l - 1] * m0;
}

__device__ __forceinline__ void do_quad(float& e, float& o, float& a2,
                                        const QB& c, float skf, float skfm,
                                        float m0, float m1) {
#pragma unroll
    for (int h = 0; h < 2; h++) {       // two fused pairs = 4 steps
        const float pm  = h ? c.pmB : c.pmA;
        const float p1a = c.p1[2 * h],     pba = c.pb[2 * h];
        const float p1b = c.p1[2 * h + 1], pbb = c.pb[2 * h + 1];
        const float x1  = shup(o, 1) * m0;
        const float x2  = shup(o, 2) * m1;
        const float y1  = shup(e, 1);
        const float otm = ((x1 + y1) + skfm * x2) * pm;
        const float et  = (e + x1) * pba;
        const float ot  = ((o + e) + skf * x1) * p1a;
        const float at  = (a2 + o) * pba;
        e  = (et + otm) * pbb;
        o  = ((ot + et) + skf * otm) * p1b;
        a2 = (at + ot) * pbb;
    }
}

__device__ __forceinline__ void rescale(float& e, float& o, float& a2,
                                        int& g, float& fpend, int& fexp) {
    e *= fpend; o *= fpend; a2 *= fpend; g += fexp;
    const int mi = warp_max_s32(__float_as_int(fmaxf(e, fmaxf(o, a2))));
    int fx = 207 - ((mi >> 23) & 0xff);              // 80 - E, exact pow2
    fx = fx > 127 ? 127 : (fx < -126 ? -126 : fx);
    fpend = __int_as_float((fx + 127) << 23);
    fexp  = fx;
}

__global__ void __launch_bounds__(160, 1)
ctc_kernel(const float* __restrict__ lp,
           const int*   __restrict__ targets,
           const int*   __restrict__ in_len,
           const int*   __restrict__ tgt_len,
           float*       __restrict__ out) {
    __shared__ float sm[256 * ROW];                 // 33792 B
    const int b   = blockIdx.x;
    const int tid = threadIdx.x;
    const int l   = tid & 31;
    const int w   = tid >> 5;
    const size_t BC = (size_t)B_SZ * C_SZ;

    const int tl   = tgt_len[b];
    const int last = in_len[b] - 1;                 // in [128, 255]
    const int c1   = (l < tl) ? targets[b * L_MAX + l] : 0;

    if (w > 0) {
        // ---- producer warp pw handles rows t = pw, pw+4, ... ----
        const int pw = w - 1;
        const float* p1p = lp + (size_t)pw * BC + (size_t)b * C_SZ + c1;
        const float* pbp = lp + (size_t)pw * BC + (size_t)b * C_SZ;
        float* srow = sm + pw * ROW;
        int r = pw;
#pragma unroll 4
        for (int k = 0; k < 64; k++) {
            if (r <= last) {
                srow[l] = __expf(__ldg(p1p));
                if (l == 0) srow[32] = __expf(__ldg(pbp));
            }
            p1p += 4 * BC; pbp += 4 * BC; srow += 4 * ROW; r += 4;
            if (k == 17) asm volatile("bar.arrive 1, 160;");   // rows < 72 done
            if (k == 33) asm volatile("bar.arrive 2, 160;");   // rows < 136
            if (k == 49) asm volatile("bar.arrive 3, 160;");   // rows < 200
        }
        asm volatile("bar.arrive 4, 160;");                    // all rows
        return;
    }

    // ---- consumer warp ----
    const int  c1p  = __shfl_up_sync(0xffffffffu, c1, 1);
    const bool skip = (c1 != 0) && ((l == 0) || (c1 != c1p));
    const float skf  = skip ? 1.f : 0.f;
    const float skfm = shup(skf, 1);
    const float m0   = (l == 0) ? 0.f : 1.f;
    const float m1   = (l <= 1) ? 0.f : 1.f;

    asm volatile("bar.sync 1, 160;" ::: "memory");  // rows < 72 available

    // t=0 init (prob domain, pre-scaled 2^80)
    float e = 0.f, o = 0.f, a2 = 0.f;
    if (l == 0) {
        e = sm[32] * 0x1p80f;
        o = (tl > 0) ? sm[0] * 0x1p80f : 0.f;
    }
    int g = 80;
    float fpend = 1.f;
    int   fexp  = 0;

    const int nq  = last >> 2;                      // in [32, 63]
    const int rem = last & 3;

    QB A, Bq;
    loadq(sm, 0, last, l, m0, A);

    int q = 0;
    for (int s = 0; s < 4; s++) {                   // 16-quad segments
        if (s > 0) {
            if (q >= nq) break;
            asm volatile("bar.sync %0, 160;" :: "r"(s + 1) : "memory");
        }
        const int qend = min(nq, 16 * (s + 1));
        while (q + 1 < qend) {                      // quads in ping/pong pairs
            rescale(e, o, a2, g, fpend, fexp);      // every 4 steps, lagged
            loadq(sm, q + 1, last, l, m0, Bq);
            do_quad(e, o, a2, A, skf, skfm, m0, m1);  q++;
            rescale(e, o, a2, g, fpend, fexp);
            loadq(sm, q + 1, last, l, m0, A);
            do_quad(e, o, a2, Bq, skf, skfm, m0, m1); q++;
        }
    }
    if (q < nq) {                                   // leftover quad (nq odd), q even
        rescale(e, o, a2, g, fpend, fexp);
        loadq(sm, q + 1, last, l, m0, Bq);
        do_quad(e, o, a2, A, skf, skfm, m0, m1);    q++;
    }

    // epilogue: rem steps, data for quad nq sits in A (nq even) or Bq (nq odd)
    float ep1[3], epb[3];
#pragma unroll
    for (int j = 0; j < 3; j++) {
        ep1[j] = (nq & 1) ? Bq.p1[j] : A.p1[j];
        epb[j] = (nq & 1) ? Bq.pb[j] : A.pb[j];
    }
#pragma unroll
    for (int j = 0; j < 3; j++) {
        if (j < rem) {
            const float x1 = shup(o, 1) * m0;
            const float en = (e + x1) * epb[j];
            const float on = ((o + e) + skf * x1) * ep1[j];
            const float an = (a2 + o) * epb[j];
            e = en; o = on; a2 = an;
        }
    }

    // final states: i_blank = 2*tl (e @ lane tl, or a2 @ lane31 if tl==32),
    //               i_char  = 2*tl-1 (o @ lane tl-1)
    const float vbl = __shfl_sync(0xffffffffu, e, tl & 31);
    const float vbh = __shfl_sync(0xffffffffu, a2, 31);
    const float vb  = (tl >= 32) ? vbh : vbl;
    const int   icl = (tl > 0) ? (tl - 1) : 0;
    const float vc  = __shfl_sync(0xffffffffu, o, icl);
    const float tot = (tl > 0) ? (vb + vc) : vb;

    if (l == 0) {
        const float total_log = logf(tot) - (float)g * 0.69314718055994531f;
        const int   denom     = (tl > 0) ? tl : 1;
        g_loss[b] = -total_log / (float)denom;
        __threadfence();
        const int old = atomicAdd(&g_count, 1);
        if (old == B_SZ - 1) {
            g_count = 0;                            // reset for next graph replay
            __threadfence();
            float s = 0.f;
            for (int i = 0; i < B_SZ; i++) s += __ldcg((const float*)&g_loss[i]);
            out[0] = s / (float)B_SZ;
        }
    }
}

extern "C" void kernel_launch(void* const* d_in, const int* in_sizes, int n_in,
                              void* d_out, int out_size) {
    const float* log_probs  = (const float*)d_in[0];
    const int*   targets    = (const int*)d_in[1];
    const int*   input_len  = (const int*)d_in[2];
    const int*   target_len = (const int*)d_in[3];
    float* out = (float*)d_out;
    (void)in_sizes; (void)n_in; (void)out_size;

    ctc_kernel<<<B_SZ, 160>>>(log_probs, targets, input_len, target_len, out);
}

// round 10
// speedup vs baseline: 1.6758x; 1.5254x over previous
#include <cuda_runtime.h>

// CTC loss forward, single fused kernel, producer/consumer within each block.
// 64 blocks (one per batch), 9 warps: warps 1-8 gather+exp emissions into a
// smem table sm[t][0..31]=exp(lp[t,b,c1(l)]), sm[t][32]=exp(lp[t,b,blank]),
// striped t%8 in groups of 9/8/8/7 rows, signalling named bars 1..4 after
// rows <72 / <136 / <200 / all (consumer segment s prefetches rows up to
// 68/132/196 — strictly covered). Warp 0 runs the linear-domain fused-pair
// recursion off LDS: lane l owns states 2l ("e") and 2l+1 ("o"); lane 31 also
// state 64 ("a2"). Exact pow2 rescale every 4 steps (redux.sync.max.s32 on
// float bits), lag-applied. smem has 1 pad row so quad loads never clamp.

constexpr int B_SZ  = 64;
constexpr int C_SZ  = 8000;
constexpr int L_MAX = 32;
constexpr int ROW   = 33;
constexpr int NPW   = 8;                 // producer warps
constexpr int NTHR  = 32 * (NPW + 1);    // 288

__device__ float g_loss[B_SZ];
__device__ int   g_count;

__device__ __forceinline__ int warp_max_s32(int v) {
    int r;
    asm volatile("redux.sync.max.s32 %0, %1, 0xffffffff;" : "=r"(r) : "r"(v));
    return r;
}
__device__ __forceinline__ float shup(float v, int d) {
    return __shfl_up_sync(0xffffffffu, v, d);
}

struct QB { float p1[4], pb[4], pmA, pmB; };

__device__ __forceinline__ void loadq(const float* __restrict__ sm, int q,
                                      int l, float m0, QB& d) {
    const int r0 = 4 * q + 1;                       // rows r0..r0+3 (pad row covers r0+3=256)
#pragma unroll
    for (int j = 0; j < 4; j++) {
        d.p1[j] = sm[(r0 + j) * ROW + l];
        d.pb[j] = sm[(r0 + j) * ROW + 32];
    }
    // l==0 reads [r*ROW-1] = previous row's blank slot; masked by m0
    d.pmA = sm[r0 * ROW + l - 1] * m0;
    d.pmB = sm[(r0 + 2) * ROW + l - 1] * m0;
}

__device__ __forceinline__ void do_quad(float& e, float& o, float& a2,
                                        const QB& c, float skf, float skfm,
                                        float m0, float m1) {
#pragma unroll
    for (int h = 0; h < 2; h++) {       // two fused pairs = 4 steps
        const float pm  = h ? c.pmB : c.pmA;
        const float p1a = c.p1[2 * h],     pba = c.pb[2 * h];
        const float p1b = c.p1[2 * h + 1], pbb = c.pb[2 * h + 1];
        const float x1  = shup(o, 1) * m0;
        const float x2  = shup(o, 2) * m1;
        const float y1  = shup(e, 1);
        const float otm = ((x1 + y1) + skfm * x2) * pm;
        const float et  = (e + x1) * pba;
        const float ot  = ((o + e) + skf * x1) * p1a;
        const float at  = (a2 + o) * pba;
        e  = (et + otm) * pbb;
        o  = ((ot + et) + skf * otm) * p1b;
        a2 = (at + ot) * pbb;
    }
}

__device__ __forceinline__ void rescale(float& e, float& o, float& a2,
                                        int& g, float& fpend, int& fexp) {
    e *= fpend; o *= fpend; a2 *= fpend; g += fexp;
    const int mi = warp_max_s32(__float_as_int(fmaxf(e, fmaxf(o, a2))));
    int fx = 207 - ((mi >> 23) & 0xff);              // 80 - E, exact pow2
    fx = fx > 127 ? 127 : (fx < -126 ? -126 : fx);
    fpend = __int_as_float((fx + 127) << 23);
    fexp  = fx;
}

__global__ void __launch_bounds__(NTHR, 1)
ctc_kernel(const float* __restrict__ lp,
           const int*   __restrict__ targets,
           const int*   __restrict__ in_len,
           const int*   __restrict__ tgt_len,
           float*       __restrict__ out) {
    __shared__ float sm[257 * ROW];                 // 256 rows + 1 pad row
    const int b   = blockIdx.x;
    const int tid = threadIdx.x;
    const int l   = tid & 31;
    const int w   = tid >> 5;
    const size_t BC = (size_t)B_SZ * C_SZ;

    const int tl   = tgt_len[b];
    const int last = in_len[b] - 1;                 // in [128, 255]
    const int c1   = (l < tl) ? targets[b * L_MAX + l] : 0;

    if (w > 0) {
        // ---- producer warp pw handles rows t = pw, pw+8, ... (32 rows) ----
        const int pw = w - 1;
        const float* pbp = lp + (size_t)pw * BC + (size_t)b * C_SZ;
        const float* p1p = pbp + c1;
        float* srow = sm + pw * ROW;
        // groups of 9/8/8/7 iterations; after group g, rows <= 8*(kend-1)+7
#pragma unroll
        for (int k = 0; k < 9; k++) {               // rows pw..pw+64  (<72)
            srow[k * 8 * ROW + l] = __expf(__ldg(p1p + (size_t)k * 8 * BC));
            if (l == 0) srow[k * 8 * ROW + 32] = __expf(__ldg(pbp + (size_t)k * 8 * BC));
        }
        asm volatile("bar.arrive 1, 288;");
#pragma unroll
        for (int k = 9; k < 17; k++) {              // rows <136
            srow[k * 8 * ROW + l] = __expf(__ldg(p1p + (size_t)k * 8 * BC));
            if (l == 0) srow[k * 8 * ROW + 32] = __expf(__ldg(pbp + (size_t)k * 8 * BC));
        }
        asm volatile("bar.arrive 2, 288;");
#pragma unroll
        for (int k = 17; k < 25; k++) {             // rows <200
            srow[k * 8 * ROW + l] = __expf(__ldg(p1p + (size_t)k * 8 * BC));
            if (l == 0) srow[k * 8 * ROW + 32] = __expf(__ldg(pbp + (size_t)k * 8 * BC));
        }
        asm volatile("bar.arrive 3, 288;");
#pragma unroll
        for (int k = 25; k < 32; k++) {             // all rows
            srow[k * 8 * ROW + l] = __expf(__ldg(p1p + (size_t)k * 8 * BC));
            if (l == 0) srow[k * 8 * ROW + 32] = __expf(__ldg(pbp + (size_t)k * 8 * BC));
        }
        asm volatile("bar.arrive 4, 288;");
        return;
    }

    // ---- consumer warp ----
    const int  c1p  = __shfl_up_sync(0xffffffffu, c1, 1);
    const bool skip = (c1 != 0) && ((l == 0) || (c1 != c1p));
    const float skf  = skip ? 1.f : 0.f;
    const float skfm = shup(skf, 1);
    const float m0   = (l == 0) ? 0.f : 1.f;
    const float m1   = (l <= 1) ? 0.f : 1.f;

    asm volatile("bar.sync 1, 288;" ::: "memory");  // rows < 72 available

    // t=0 init (prob domain, pre-scaled 2^80)
    float e = 0.f, o = 0.f, a2 = 0.f;
    if (l == 0) {
        e = sm[32] * 0x1p80f;
        o = (tl > 0) ? sm[0] * 0x1p80f : 0.f;
    }
    int g = 80;
    float fpend = 1.f;
    int   fexp  = 0;

    const int nq  = last >> 2;                      // in [32, 63]
    const int rem = last & 3;

    QB A, Bq;
    loadq(sm, 0, l, m0, A);

    int q = 0;
    for (int s = 0; s < 4; s++) {                   // 16-quad segments
        if (s > 0) {
            if (q >= nq) break;
            asm volatile("bar.sync %0, 288;" :: "r"(s + 1) : "memory");
        }
        const int qend = min(nq, 16 * (s + 1));
        while (q + 1 < qend) {                      // quads in ping/pong pairs
            rescale(e, o, a2, g, fpend, fexp);      // every 4 steps, lagged
            loadq(sm, q + 1, l, m0, Bq);
            do_quad(e, o, a2, A, skf, skfm, m0, m1);  q++;
            rescale(e, o, a2, g, fpend, fexp);
            loadq(sm, q + 1, l, m0, A);
            do_quad(e, o, a2, Bq, skf, skfm, m0, m1); q++;
        }
    }
    if (q < nq) {                                   // leftover quad (nq odd), q even
        rescale(e, o, a2, g, fpend, fexp);
        loadq(sm, q + 1, l, m0, Bq);
        do_quad(e, o, a2, A, skf, skfm, m0, m1);    q++;
    }

    // epilogue: rem steps, data for quad nq sits in A (nq even) or Bq (nq odd)
    float ep1[3], epb[3];
#pragma unroll
    for (int j = 0; j < 3; j++) {
        ep1[j] = (nq & 1) ? Bq.p1[j] : A.p1[j];
        epb[j] = (nq & 1) ? Bq.pb[j] : A.pb[j];
    }
#pragma unroll
    for (int j = 0; j < 3; j++) {
        if (j < rem) {
            const float x1 = shup(o, 1) * m0;
            const float en = (e + x1) * epb[j];
            const float on = ((o + e) + skf * x1) * ep1[j];
            const float an = (a2 + o) * epb[j];
            e = en; o = on; a2 = an;
        }
    }

    // final states: i_blank = 2*tl (e @ lane tl, or a2 @ lane31 if tl==32),
    //               i_char  = 2*tl-1 (o @ lane tl-1)
    const float vbl = __shfl_sync(0xffffffffu, e, tl & 31);
    const float vbh = __shfl_sync(0xffffffffu, a2, 31);
    const float vb  = (tl >= 32) ? vbh : vbl;
    const int   icl = (tl > 0) ? (tl - 1) : 0;
    const float vc  = __shfl_sync(0xffffffffu, o, icl);
    const float tot = (tl > 0) ? (vb + vc) : vb;

    if (l == 0) {
        const float total_log = logf(tot) - (float)g * 0.69314718055994531f;
        const int   denom     = (tl > 0) ? tl : 1;
        g_loss[b] = -total_log / (float)denom;
        __threadfence();
        const int old = atomicAdd(&g_count, 1);
        if (old == B_SZ - 1) {
            g_count = 0;                            // reset for next graph replay
            __threadfence();
            float s = 0.f;
            for (int i = 0; i < B_SZ; i++) s += __ldcg((const float*)&g_loss[i]);
            out[0] = s / (float)B_SZ;
        }
    }
}

extern "C" void kernel_launch(void* const* d_in, const int* in_sizes, int n_in,
                              void* d_out, int out_size) {
    const float* log_probs  = (const float*)d_in[0];
    const int*   targets    = (const int*)d_in[1];
    const int*   input_len  = (const int*)d_in[2];
    const int*   target_len = (const int*)d_in[3];
    float* out = (float*)d_out;
    (void)in_sizes; (void)n_in; (void)out_size;

    ctc_kernel<<<B_SZ, NTHR>>>(log_probs, targets, input_len, target_len, out);
}

// round 11
// speedup vs baseline: 1.7500x; 1.0442x over previous
#include <cuda_runtime.h>

// CTC loss forward, single fused kernel, producer/consumer within each block.
// 64 blocks (one per batch), 9 warps. Warps 1-8 gather+exp emissions into
// smem sm[t][0..31]=exp(lp[t,b,c1(l)]), sm[t][32]=exp(lp[t,b,blank]), rows
// striped t%8. Fine-grained named barriers: id 1 after each warp's row k=0,
// id s+2 (s=0..6) after rows k<=4s+4 (=> rows <= 32s+39 written), id 9 after
// all rows. Producer groups batch 8 LDGs into registers before exp+STS (MLP).
// Warp 0: linear-domain fused-pair recursion off LDS; lane l owns states 2l
// ("e"), 2l+1 ("o"); lane 31 also state 64 ("a2"). Segment s (8 quads) waits
// bar s+2 (prefetch bound 32s+36 <= 32s+39). Exact pow2 rescale every 4 steps
// (redux.sync.max.s32 on float bits), lag-applied.

constexpr int B_SZ  = 64;
constexpr int C_SZ  = 8000;
constexpr int L_MAX = 32;
constexpr int ROW   = 33;
constexpr int NTHR  = 288;               // 1 consumer + 8 producer warps

__device__ float g_loss[B_SZ];
__device__ int   g_count;

__device__ __forceinline__ int warp_max_s32(int v) {
    int r;
    asm volatile("redux.sync.max.s32 %0, %1, 0xffffffff;" : "=r"(r) : "r"(v));
    return r;
}
__device__ __forceinline__ float shup(float v, int d) {
    return __shfl_up_sync(0xffffffffu, v, d);
}

struct QB { float p1[4], pb[4], pmA, pmB; };

__device__ __forceinline__ void loadq(const float* __restrict__ sm, int q,
                                      int l, float m0, QB& d) {
    const int r0 = 4 * q + 1;            // rows r0..r0+3; pad row covers 256
#pragma unroll
    for (int j = 0; j < 4; j++) {
        d.p1[j] = sm[(r0 + j) * ROW + l];
        d.pb[j] = sm[(r0 + j) * ROW + 32];
    }
    // l==0 reads [r*ROW-1] = previous row's blank slot; masked by m0
    d.pmA = sm[r0 * ROW + l - 1] * m0;
    d.pmB = sm[(r0 + 2) * ROW + l - 1] * m0;
}

__device__ __forceinline__ void do_quad(float& e, float& o, float& a2,
                                        const QB& c, float skf, float skfm,
                                        float m0, float m1) {
#pragma unroll
    for (int h = 0; h < 2; h++) {        // two fused pairs = 4 steps
        const float pm  = h ? c.pmB : c.pmA;
        const float p1a = c.p1[2 * h],     pba = c.pb[2 * h];
        const float p1b = c.p1[2 * h + 1], pbb = c.pb[2 * h + 1];
        const float x1  = shup(o, 1) * m0;
        const float x2  = shup(o, 2) * m1;
        const float y1  = shup(e, 1);
        const float otm = ((x1 + y1) + skfm * x2) * pm;
        const float et  = (e + x1) * pba;
        const float ot  = ((o + e) + skf * x1) * p1a;
        const float at  = (a2 + o) * pba;
        e  = (et + otm) * pbb;
        o  = ((ot + et) + skf * otm) * p1b;
        a2 = (at + ot) * pbb;
    }
}

__device__ __forceinline__ void rescale(float& e, float& o, float& a2,
                                        int& g, float& fpend, int& fexp) {
    e *= fpend; o *= fpend; a2 *= fpend; g += fexp;
    const int mi = warp_max_s32(__float_as_int(fmaxf(e, fmaxf(o, a2))));
    int fx = 207 - ((mi >> 23) & 0xff);              // 80 - E, exact pow2
    fx = fx > 127 ? 127 : (fx < -126 ? -126 : fx);
    fpend = __int_as_float((fx + 127) << 23);
    fexp  = fx;
}

__global__ void __launch_bounds__(NTHR, 1)
ctc_kernel(const float* __restrict__ lp,
           const int*   __restrict__ targets,
           const int*   __restrict__ in_len,
           const int*   __restrict__ tgt_len,
           float*       __restrict__ out) {
    __shared__ float sm[257 * ROW];                 // 256 rows + 1 pad row
    const int b   = blockIdx.x;
    const int tid = threadIdx.x;
    const int l   = tid & 31;
    const int w   = tid >> 5;
    const size_t BC = (size_t)B_SZ * C_SZ;

    const int tl   = tgt_len[b];
    const int last = in_len[b] - 1;                 // in [128, 255]
    const int c1   = (l < tl) ? targets[b * L_MAX + l] : 0;

    if (w > 0) {
        // ---- producer warp pw: rows t = pw + 8k, k = 0..31 ----
        const int pw = w - 1;
        const float* pbp = lp + (size_t)pw * BC + (size_t)b * C_SZ;
        const float* p1p = pbp + c1;
        float* srow = sm + pw * ROW;

        {   // k = 0 -> barrier 1 (rows <= 7)
            const float v1 = __ldg(p1p);
            const float vb = __ldg(pbp);
            srow[l] = __expf(v1);
            if (l == 0) srow[32] = __expf(vb);
            asm volatile("bar.arrive 1, 288;" ::: "memory");
        }
#pragma unroll
        for (int s = 0; s < 7; s++) {               // k = 4s+1..4s+4 -> bar s+2
            float v1[4], vb[4];
#pragma unroll
            for (int j = 0; j < 4; j++) {
                const size_t off = (size_t)(4 * s + 1 + j) * 8 * BC;
                v1[j] = __ldg(p1p + off);
                vb[j] = __ldg(pbp + off);
            }
#pragma unroll
            for (int j = 0; j < 4; j++) {
                const int k = 4 * s + 1 + j;
                srow[k * 8 * ROW + l] = __expf(v1[j]);
                if (l == 0) srow[k * 8 * ROW + 32] = __expf(vb[j]);
            }
            asm volatile("bar.arrive %0, 288;" :: "r"(s + 2) : "memory");
        }
        {   // k = 29..31 -> barrier 9 (all rows)
            float v1[3], vb[3];
#pragma unroll
            for (int j = 0; j < 3; j++) {
                const size_t off = (size_t)(29 + j) * 8 * BC;
                v1[j] = __ldg(p1p + off);
                vb[j] = __ldg(pbp + off);
            }
#pragma unroll
            for (int j = 0; j < 3; j++) {
                const int k = 29 + j;
                srow[k * 8 * ROW + l] = __expf(v1[j]);
                if (l == 0) srow[k * 8 * ROW + 32] = __expf(vb[j]);
            }
            asm volatile("bar.arrive 9, 288;" ::: "memory");
        }
        return;
    }

    // ---- consumer warp ----
    const int  c1p  = __shfl_up_sync(0xffffffffu, c1, 1);
    const bool skip = (c1 != 0) && ((l == 0) || (c1 != c1p));
    const float skf  = skip ? 1.f : 0.f;
    const float skfm = shup(skf, 1);
    const float m0   = (l == 0) ? 0.f : 1.f;
    const float m1   = (l <= 1) ? 0.f : 1.f;

    asm volatile("bar.sync 1, 288;" ::: "memory");  // rows <= 7 available

    // t=0 init (prob domain, pre-scaled 2^80)
    float e = 0.f, o = 0.f, a2 = 0.f;
    if (l == 0) {
        e = sm[32] * 0x1p80f;
        o = (tl > 0) ? sm[0] * 0x1p80f : 0.f;
    }
    int g = 80;
    float fpend = 1.f;
    int   fexp  = 0;

    const int nq  = last >> 2;                      // in [32, 63]
    const int rem = last & 3;

    QB A, Bq;
    loadq(sm, 0, l, m0, A);

    int q = 0;
#pragma unroll 1
    for (int s = 0; s < 7; s++) {                   // 8-quad segments
        if (q + 1 >= nq) break;                     // only leftover/epilogue left
        asm volatile("bar.sync %0, 288;" :: "r"(s + 2) : "memory");
        const int qend = min(nq, 8 * (s + 1));
        while (q + 1 < qend) {                      // quads in ping/pong pairs
            rescale(e, o, a2, g, fpend, fexp);      // every 4 steps, lagged
            loadq(sm, q + 1, l, m0, Bq);
            do_quad(e, o, a2, A, skf, skfm, m0, m1);  q++;
            rescale(e, o, a2, g, fpend, fexp);
            loadq(sm, q + 1, l, m0, A);
            do_quad(e, o, a2, Bq, skf, skfm, m0, m1); q++;
        }
    }
    if (q < nq) {                                   // tail region: all rows ready
        asm volatile("bar.sync 9, 288;" ::: "memory");
        while (q + 1 < nq) {
            rescale(e, o, a2, g, fpend, fexp);
            loadq(sm, q + 1, l, m0, Bq);
            do_quad(e, o, a2, A, skf, skfm, m0, m1);  q++;
            rescale(e, o, a2, g, fpend, fexp);
            loadq(sm, q + 1, l, m0, A);
            do_quad(e, o, a2, Bq, skf, skfm, m0, m1); q++;
        }
        if (q < nq) {                               // leftover quad (nq odd)
            rescale(e, o, a2, g, fpend, fexp);
            loadq(sm, q + 1, l, m0, Bq);
            do_quad(e, o, a2, A, skf, skfm, m0, m1); q++;
        }
    }

    // epilogue: rem steps; quad-nq data sits in A (nq even) or Bq (nq odd)
    float ep1[3], epb[3];
#pragma unroll
    for (int j = 0; j < 3; j++) {
        ep1[j] = (nq & 1) ? Bq.p1[j] : A.p1[j];
        epb[j] = (nq & 1) ? Bq.pb[j] : A.pb[j];
    }
#pragma unroll
    for (int j = 0; j < 3; j++) {
        if (j < rem) {
            const float x1 = shup(o, 1) * m0;
            const float en = (e + x1) * epb[j];
            const float on = ((o + e) + skf * x1) * ep1[j];
            const float an = (a2 + o) * epb[j];
            e = en; o = on; a2 = an;
        }
    }

    // final states: i_blank = 2*tl (e @ lane tl, or a2 @ lane31 if tl==32),
    //               i_char  = 2*tl-1 (o @ lane tl-1)
    const float vbl = __shfl_sync(0xffffffffu, e, tl & 31);
    const float vbh = __shfl_sync(0xffffffffu, a2, 31);
    const float vb  = (tl >= 32) ? vbh : vbl;
    const int   icl = (tl > 0) ? (tl - 1) : 0;
    const float vc  = __shfl_sync(0xffffffffu, o, icl);
    const float tot = (tl > 0) ? (vb + vc) : vb;

    if (l == 0) {
        const float total_log = logf(tot) - (float)g * 0.69314718055994531f;
        const int   denom     = (tl > 0) ? tl : 1;
        g_loss[b] = -total_log / (float)denom;
        __threadfence();
        const int old = atomicAdd(&g_count, 1);
        if (old == B_SZ - 1) {
            g_count = 0;                            // reset for next graph replay
            __threadfence();
            float s = 0.f;
            for (int i = 0; i < B_SZ; i++) s += __ldcg((const float*)&g_loss[i]);
            out[0] = s / (float)B_SZ;
        }
    }
}

extern "C" void kernel_launch(void* const* d_in, const int* in_sizes, int n_in,
                              void* d_out, int out_size) {
    const float* log_probs  = (const float*)d_in[0];
    const int*   targets    = (const int*)d_in[1];
    const int*   input_len  = (const int*)d_in[2];
    const int*   target_len = (const int*)d_in[3];
    float* out = (float*)d_out;
    (void)in_sizes; (void)n_in; (void)out_size;

    ctc_kernel<<<B_SZ, NTHR>>>(log_probs, targets, input_len, target_len, out);
}